// round 2
// baseline (speedup 1.0000x reference)
#include <cuda_runtime.h>
#include <math.h>

#define BB 32
#define NN 577
#define CC 768
#define HH 12
#define DD 64
#define MM (BB*NN)      // 18464
#define KDIM 768
#define QKV_N 2304
#define NTILES ((NN + 63) / 64)   // 10

// ---------------- scratch (no allocations allowed) ----------------
__device__ float g_q[BB*HH*NN*DD];   // [B,H,N,D]
__device__ float g_k[BB*HH*NN*DD];
__device__ float g_v[BB*HH*NN*DD];
__device__ float g_o[MM*CC];         // attention output, [B*N, C]

// ---------------- SGEMM: C[M, Nout] = A[M,K] * W[Nout,K]^T ----------------
// MODE 0: A = x, W = qkv_w, scatter into g_q/g_k/g_v with bias
// MODE 1: A = g_o, W = proj_w, write out + proj_b
template<int MODE>
__global__ __launch_bounds__(256) void sgemm_kernel(
    const float* __restrict__ A_in, const float* __restrict__ W,
    const float* __restrict__ bias_q, const float* __restrict__ bias_v,
    float* __restrict__ out)
{
    __shared__ float As[16*64];   // [k][m]
    __shared__ float Bs[16*64];   // [k][o]

    const float* A = (MODE == 1) ? (const float*)g_o : A_in;

    int tid = threadIdx.x;
    int tx = tid & 15, ty = tid >> 4;
    int m0 = blockIdx.y * 64;
    int n0 = blockIdx.x * 64;
    int lr = tid >> 2;          // 0..63
    int lk = (tid & 3) * 4;     // 0,4,8,12

    float acc[4][4] = {};

    for (int k0 = 0; k0 < KDIM; k0 += 16) {
        int am = m0 + lr;
        float4 av = make_float4(0.f, 0.f, 0.f, 0.f);
        if (am < MM) av = *(const float4*)&A[am*KDIM + k0 + lk];
        As[(lk+0)*64 + lr] = av.x;
        As[(lk+1)*64 + lr] = av.y;
        As[(lk+2)*64 + lr] = av.z;
        As[(lk+3)*64 + lr] = av.w;

        float4 bv = *(const float4*)&W[(n0 + lr)*KDIM + k0 + lk];
        Bs[(lk+0)*64 + lr] = bv.x;
        Bs[(lk+1)*64 + lr] = bv.y;
        Bs[(lk+2)*64 + lr] = bv.z;
        Bs[(lk+3)*64 + lr] = bv.w;

        __syncthreads();

        #pragma unroll
        for (int k = 0; k < 16; k++) {
            float4 a4 = *(const float4*)&As[k*64 + ty*4];
            float4 b4 = *(const float4*)&Bs[k*64 + tx*4];
            float a[4] = {a4.x, a4.y, a4.z, a4.w};
            float b[4] = {b4.x, b4.y, b4.z, b4.w};
            #pragma unroll
            for (int i = 0; i < 4; i++)
                #pragma unroll
                for (int j = 0; j < 4; j++)
                    acc[i][j] += a[i] * b[j];
        }
        __syncthreads();
    }

    int o = n0 + tx*4;

    if (MODE == 0) {
        int which = o / CC;          // 0=q, 1=k, 2=v
        int rem   = o % CC;
        int h     = rem / DD;
        int d     = rem % DD;        // multiple of 4
        float bj[4];
        #pragma unroll
        for (int j = 0; j < 4; j++) {
            bj[j] = (which == 0) ? bias_q[rem + j]
                  : (which == 2) ? bias_v[rem + j] : 0.f;
        }
        float* dst = (which == 0) ? g_q : (which == 1) ? g_k : g_v;
        #pragma unroll
        for (int i = 0; i < 4; i++) {
            int m = m0 + ty*4 + i;
            if (m >= MM) break;
            int bb = m / NN, n = m % NN;
            float4 r = make_float4(acc[i][0] + bj[0], acc[i][1] + bj[1],
                                   acc[i][2] + bj[2], acc[i][3] + bj[3]);
            *(float4*)&dst[((bb*HH + h)*NN + n)*DD + d] = r;
        }
    } else {
        float4 pb = *(const float4*)&bias_q[o];   // proj_b passed via bias_q
        #pragma unroll
        for (int i = 0; i < 4; i++) {
            int m = m0 + ty*4 + i;
            if (m >= MM) break;
            float4 r = make_float4(acc[i][0] + pb.x, acc[i][1] + pb.y,
                                   acc[i][2] + pb.z, acc[i][3] + pb.w);
            *(float4*)&out[m*CC + o] = r;
        }
    }
}

// ---------------- RoPE (in-place on g_q, g_k, tokens 1..N-1) ----------------
__global__ void rope_kernel(const float* __restrict__ rope)
{
    int idx = blockIdx.x * blockDim.x + threadIdx.x;
    const int total = BB*HH*(NN-1)*(DD/2);
    if (idx >= total) return;
    int pair = idx & 31;            // DD/2 = 32
    int rest = idx >> 5;
    int nr = rest % (NN-1);
    int bh = rest / (NN-1);
    int d0 = pair * 2;

    float s0 = rope[nr*2*DD + d0];
    float s1 = rope[nr*2*DD + d0 + 1];
    float c0 = rope[nr*2*DD + DD + d0];
    float c1 = rope[nr*2*DD + DD + d0 + 1];

    int base = (bh*NN + (nr + 1))*DD + d0;
    float2 q = *(float2*)&g_q[base];
    float2 k = *(float2*)&g_k[base];
    *(float2*)&g_q[base] = make_float2(q.x*c0 - q.y*s0, q.y*c1 + q.x*s1);
    *(float2*)&g_k[base] = make_float2(k.x*c0 - k.y*s0, k.y*c1 + k.x*s1);
}

// ---------------- Flash attention ----------------
// grid: (NTILES, B*H), block 256 threads.
// smem: Qs[64][64], Kst[64(d)][65(c)], Vs[64][64], Ps[64][64]
#define ATTN_SMEM ((4096 + 64*65 + 4096 + 4096) * 4)

__global__ __launch_bounds__(256) void attn_kernel()
{
    extern __shared__ float sm[];
    float* Qs  = sm;                   // 4096
    float* Kst = sm + 4096;            // 64*65 = 4160, [d][c] stride 65
    float* Vs  = Kst + 64*65;          // 4096, [c][d]
    float* Ps  = Vs + 4096;            // 4096, [r][c]

    int tid = threadIdx.x;
    int tx = tid & 15, ty = tid >> 4;
    int bh = blockIdx.y;
    int q0 = blockIdx.x * 64;
    const float scale = 0.125f;        // D^-0.5
    int base = bh * NN * DD;

    // load Q tile (scaled), coalesced float4
    #pragma unroll
    for (int s = 0; s < 4; s++) {
        int e = tid + 256*s;          // float4 index 0..1023
        int r = e >> 4;
        int d = (e & 15) * 4;
        float4 v = make_float4(0.f, 0.f, 0.f, 0.f);
        if (q0 + r < NN) v = *(const float4*)&g_q[base + (q0 + r)*DD + d];
        v.x *= scale; v.y *= scale; v.z *= scale; v.w *= scale;
        *(float4*)&Qs[r*64 + d] = v;
    }

    float m_i[4], l_i[4], acc[4][4];
    #pragma unroll
    for (int i = 0; i < 4; i++) {
        m_i[i] = -1e30f; l_i[i] = 0.f;
        #pragma unroll
        for (int j = 0; j < 4; j++) acc[i][j] = 0.f;
    }

    for (int t0 = 0; t0 < NN; t0 += 64) {
        __syncthreads();   // protect smem reuse (also covers initial Q writes)

        // load K (transposed into Kst) and V (natural)
        #pragma unroll
        for (int s = 0; s < 4; s++) {
            int e = tid + 256*s;
            int c = e >> 4;
            int d = (e & 15) * 4;
            float4 kv = make_float4(0.f, 0.f, 0.f, 0.f);
            float4 vv = kv;
            if (t0 + c < NN) {
                kv = *(const float4*)&g_k[base + (t0 + c)*DD + d];
                vv = *(const float4*)&g_v[base + (t0 + c)*DD + d];
            }
            Kst[(d+0)*65 + c] = kv.x;
            Kst[(d+1)*65 + c] = kv.y;
            Kst[(d+2)*65 + c] = kv.z;
            Kst[(d+3)*65 + c] = kv.w;
            *(float4*)&Vs[c*64 + d] = vv;
        }
        __syncthreads();

        // scores: s4[i][j] = Q[ty*4+i] . K[tx*4+j]
        float s4[4][4];
        #pragma unroll
        for (int i = 0; i < 4; i++)
            #pragma unroll
            for (int j = 0; j < 4; j++) s4[i][j] = 0.f;

        #pragma unroll 16
        for (int kk = 0; kk < 64; kk++) {
            float qv[4], kvr[4];
            #pragma unroll
            for (int i = 0; i < 4; i++) qv[i] = Qs[(ty*4 + i)*64 + kk];
            #pragma unroll
            for (int j = 0; j < 4; j++) kvr[j] = Kst[kk*65 + tx*4 + j];
            #pragma unroll
            for (int i = 0; i < 4; i++)
                #pragma unroll
                for (int j = 0; j < 4; j++) s4[i][j] += qv[i] * kvr[j];
        }

        // online softmax per row (reduce across 16 tx lanes)
        int cbase = t0 + tx*4;
        #pragma unroll
        for (int i = 0; i < 4; i++) {
            #pragma unroll
            for (int j = 0; j < 4; j++)
                if (cbase + j >= NN) s4[i][j] = -1e30f;
            float mloc = fmaxf(fmaxf(s4[i][0], s4[i][1]), fmaxf(s4[i][2], s4[i][3]));
            #pragma unroll
            for (int off = 8; off >= 1; off >>= 1)
                mloc = fmaxf(mloc, __shfl_xor_sync(0xffffffffu, mloc, off));
            float mnew = fmaxf(m_i[i], mloc);
            float corr = __expf(m_i[i] - mnew);
            m_i[i] = mnew;
            float p[4], ps = 0.f;
            #pragma unroll
            for (int j = 0; j < 4; j++) { p[j] = __expf(s4[i][j] - mnew); ps += p[j]; }
            #pragma unroll
            for (int off = 8; off >= 1; off >>= 1)
                ps += __shfl_xor_sync(0xffffffffu, ps, off);
            l_i[i] = l_i[i]*corr + ps;
            #pragma unroll
            for (int j = 0; j < 4; j++) acc[i][j] *= corr;
            *(float4*)&Ps[(ty*4 + i)*64 + tx*4] = make_float4(p[0], p[1], p[2], p[3]);
        }
        __syncthreads();

        // acc += P @ V   (rows ty*4+i, dims tx*4+j)
        #pragma unroll 8
        for (int c = 0; c < 64; c++) {
            float4 vv = *(const float4*)&Vs[c*64 + tx*4];
            #pragma unroll
            for (int i = 0; i < 4; i++) {
                float p = Ps[(ty*4 + i)*64 + c];
                acc[i][0] += p * vv.x;
                acc[i][1] += p * vv.y;
                acc[i][2] += p * vv.z;
                acc[i][3] += p * vv.w;
            }
        }
    }

    // write out into [B, N, C] layout
    int b = bh / HH, h = bh % HH;
    #pragma unroll
    for (int i = 0; i < 4; i++) {
        int r = q0 + ty*4 + i;
        if (r < NN) {
            float inv = 1.f / l_i[i];
            float4 o = make_float4(acc[i][0]*inv, acc[i][1]*inv,
                                   acc[i][2]*inv, acc[i][3]*inv);
            *(float4*)&g_o[(b*NN + r)*CC + h*DD + tx*4] = o;
        }
    }
}

// ---------------- launch ----------------
extern "C" void kernel_launch(void* const* d_in, const int* in_sizes, int n_in,
                              void* d_out, int out_size)
{
    const float* x      = (const float*)d_in[0];
    const float* rope   = (const float*)d_in[1];
    const float* qkv_w  = (const float*)d_in[2];
    const float* q_bias = (const float*)d_in[3];
    const float* v_bias = (const float*)d_in[4];
    const float* proj_w = (const float*)d_in[5];
    const float* proj_b = (const float*)d_in[6];
    float* out = (float*)d_out;

    cudaFuncSetAttribute(attn_kernel,
                         cudaFuncAttributeMaxDynamicSharedMemorySize, ATTN_SMEM);

    // 1. QKV GEMM -> g_q, g_k, g_v (with bias)
    sgemm_kernel<0><<<dim3(QKV_N/64, (MM + 63)/64), 256>>>(x, qkv_w, q_bias, v_bias, nullptr);

    // 2. RoPE in place on q, k
    int rtot = BB*HH*(NN-1)*(DD/2);
    rope_kernel<<<(rtot + 255)/256, 256>>>(rope);

    // 3. attention -> g_o
    attn_kernel<<<dim3(NTILES, BB*HH), 256, ATTN_SMEM>>>();

    // 4. output projection -> d_out
    sgemm_kernel<1><<<dim3(CC/64, (MM + 63)/64), 256>>>(nullptr, proj_w, proj_b, nullptr, out);
}

// round 4
// speedup vs baseline: 1.9503x; 1.9503x over previous
#include <cuda_runtime.h>
#include <stdint.h>
#include <math.h>

#define BB 32
#define NN 577
#define CC 768
#define HH 12
#define DD 64
#define MM (BB*NN)      // 18464
#define KDIM 768
#define QKV_N 2304
#define NTILES ((NN + 63) / 64)   // 10

// ---------------- scratch ----------------
__device__ float g_q[BB*HH*NN*DD];   // [B,H,N,D]
__device__ float g_k[BB*HH*NN*DD];
__device__ float g_v[BB*HH*NN*DD];
__device__ float g_o[MM*CC];         // attention output, [B*N, C]

__device__ __forceinline__ float to_tf32(float x) {
    uint32_t u;
    asm("cvt.rna.tf32.f32 %0, %1;" : "=r"(u) : "f"(x));
    return __uint_as_float(u);
}

// ---------------- tf32 tensor-core GEMM ----------------
// C[M, Nout] = A[M,K] * W[Nout,K]^T  (+bias, scatter per MODE)
// Tile 128x128x32, 256 threads = 8 warps (2m x 4n), each warp 64x32.
// MODE 0: A = x, W = qkv_w -> g_q/g_k/g_v with bias
// MODE 1: A = g_o, W = proj_w -> out + proj_b
#define SA 36   // smem row stride (32 + 4 pad): conflict-free frags & stores

template<int MODE>
__global__ __launch_bounds__(256) void mma_gemm(
    const float* __restrict__ A_in, const float* __restrict__ W,
    const float* __restrict__ bias_q, const float* __restrict__ bias_v,
    float* __restrict__ out)
{
    __shared__ float As[128*SA];
    __shared__ float Bs[128*SA];

    const float* A = (MODE == 1) ? (const float*)g_o : A_in;

    const int tid  = threadIdx.x;
    const int lane = tid & 31;
    const int warp = tid >> 5;
    const int wm   = (warp >> 2) * 64;   // warp m-origin in tile
    const int wn   = (warp & 3) * 32;    // warp n-origin in tile
    const int r    = lane >> 2;          // 0..7
    const int cg   = lane & 3;           // 0..3

    const int m0 = blockIdx.y * 128;
    const int n0 = blockIdx.x * 128;

    // staging index: each thread moves 4 float4 per matrix per k-chunk
    const int sm_ = tid >> 1;                 // row 0..127
    const int skq = (tid & 1) * 16;           // k offset 0 or 16 (4 f4 each)

    float acc[4][4][4];
    #pragma unroll
    for (int i = 0; i < 4; i++)
        #pragma unroll
        for (int j = 0; j < 4; j++)
            #pragma unroll
            for (int q = 0; q < 4; q++) acc[i][j][q] = 0.f;

    float4 pa[4], pb[4];

    // prologue: load k-chunk 0
    {
        int gm = m0 + sm_;
        #pragma unroll
        for (int s = 0; s < 4; s++) {
            pa[s] = (gm < MM) ? *(const float4*)&A[(size_t)gm*KDIM + skq + s*4]
                              : make_float4(0.f,0.f,0.f,0.f);
            pb[s] = *(const float4*)&W[(size_t)(n0 + sm_)*KDIM + skq + s*4];
        }
    }

    const int NK = KDIM / 32;   // 24
    for (int kt = 0; kt < NK; kt++) {
        // store staged chunk (tf32-rounded)
        #pragma unroll
        for (int s = 0; s < 4; s++) {
            float4 a = pa[s], b = pb[s];
            float* pA = &As[sm_*SA + skq + s*4];
            pA[0] = to_tf32(a.x); pA[1] = to_tf32(a.y);
            pA[2] = to_tf32(a.z); pA[3] = to_tf32(a.w);
            float* pB = &Bs[sm_*SA + skq + s*4];
            pB[0] = to_tf32(b.x); pB[1] = to_tf32(b.y);
            pB[2] = to_tf32(b.z); pB[3] = to_tf32(b.w);
        }
        __syncthreads();

        // prefetch next chunk
        if (kt + 1 < NK) {
            int k0 = (kt + 1) * 32;
            int gm = m0 + sm_;
            #pragma unroll
            for (int s = 0; s < 4; s++) {
                pa[s] = (gm < MM) ? *(const float4*)&A[(size_t)gm*KDIM + k0 + skq + s*4]
                                  : make_float4(0.f,0.f,0.f,0.f);
                pb[s] = *(const float4*)&W[(size_t)(n0 + sm_)*KDIM + k0 + skq + s*4];
            }
        }

        // compute: 4 k-steps of 8
        #pragma unroll
        for (int kk = 0; kk < 32; kk += 8) {
            uint32_t af[4][4], bf[4][2];
            #pragma unroll
            for (int mt = 0; mt < 4; mt++) {
                const float* p = &As[(wm + mt*16 + r)*SA + kk + cg];
                af[mt][0] = __float_as_uint(p[0]);
                af[mt][1] = __float_as_uint(p[8*SA]);
                af[mt][2] = __float_as_uint(p[4]);
                af[mt][3] = __float_as_uint(p[8*SA + 4]);
            }
            #pragma unroll
            for (int nt = 0; nt < 4; nt++) {
                const float* p = &Bs[(wn + nt*8 + r)*SA + kk + cg];
                bf[nt][0] = __float_as_uint(p[0]);
                bf[nt][1] = __float_as_uint(p[4]);
            }
            #pragma unroll
            for (int mt = 0; mt < 4; mt++)
                #pragma unroll
                for (int nt = 0; nt < 4; nt++) {
                    asm volatile(
                        "mma.sync.aligned.m16n8k8.row.col.f32.tf32.tf32.f32 "
                        "{%0,%1,%2,%3},{%4,%5,%6,%7},{%8,%9},{%0,%1,%2,%3};"
                        : "+f"(acc[mt][nt][0]), "+f"(acc[mt][nt][1]),
                          "+f"(acc[mt][nt][2]), "+f"(acc[mt][nt][3])
                        : "r"(af[mt][0]), "r"(af[mt][1]),
                          "r"(af[mt][2]), "r"(af[mt][3]),
                          "r"(bf[nt][0]), "r"(bf[nt][1]));
                }
        }
        __syncthreads();
    }

    // ---------------- epilogue ----------------
    #pragma unroll
    for (int nt = 0; nt < 4; nt++) {
        int col = n0 + wn + nt*8 + 2*cg;     // even, pair (col, col+1)
        if (MODE == 0) {
            int which = col / CC;            // block lies in a single which
            int rem   = col - which*CC;
            int h     = rem >> 6;
            int d     = rem & 63;
            float b0 = (which == 0) ? bias_q[rem]   : (which == 2) ? bias_v[rem]   : 0.f;
            float b1 = (which == 0) ? bias_q[rem+1] : (which == 2) ? bias_v[rem+1] : 0.f;
            float* dst = (which == 0) ? g_q : (which == 1) ? g_k : g_v;
            #pragma unroll
            for (int mt = 0; mt < 4; mt++) {
                #pragma unroll
                for (int half = 0; half < 2; half++) {
                    int m = m0 + wm + mt*16 + r + half*8;
                    if (m < MM) {
                        int bb = m / NN, n = m - bb*NN;
                        float2 v = make_float2(acc[mt][nt][half*2]   + b0,
                                               acc[mt][nt][half*2+1] + b1);
                        *(float2*)&dst[(((size_t)bb*HH + h)*NN + n)*DD + d] = v;
                    }
                }
            }
        } else {
            float b0 = bias_q[col], b1 = bias_q[col+1];   // proj_b via bias_q
            #pragma unroll
            for (int mt = 0; mt < 4; mt++) {
                #pragma unroll
                for (int half = 0; half < 2; half++) {
                    int m = m0 + wm + mt*16 + r + half*8;
                    if (m < MM) {
                        float2 v = make_float2(acc[mt][nt][half*2]   + b0,
                                               acc[mt][nt][half*2+1] + b1);
                        *(float2*)&out[(size_t)m*CC + col] = v;
                    }
                }
            }
        }
    }
}

// ---------------- RoPE ----------------
__global__ void rope_kernel(const float* __restrict__ rope)
{
    int idx = blockIdx.x * blockDim.x + threadIdx.x;
    const int total = BB*HH*(NN-1)*(DD/2);
    if (idx >= total) return;
    int pair = idx & 31;
    int rest = idx >> 5;
    int nr = rest % (NN-1);
    int bh = rest / (NN-1);
    int d0 = pair * 2;

    float s0 = rope[nr*2*DD + d0];
    float s1 = rope[nr*2*DD + d0 + 1];
    float c0 = rope[nr*2*DD + DD + d0];
    float c1 = rope[nr*2*DD + DD + d0 + 1];

    int base = (bh*NN + (nr + 1))*DD + d0;
    float2 q = *(float2*)&g_q[base];
    float2 k = *(float2*)&g_k[base];
    *(float2*)&g_q[base] = make_float2(q.x*c0 - q.y*s0, q.y*c1 + q.x*s1);
    *(float2*)&g_k[base] = make_float2(k.x*c0 - k.y*s0, k.y*c1 + k.x*s1);
}

// ---------------- Flash attention (SIMT fp32) ----------------
#define ATTN_SMEM ((4096 + 64*65 + 4096 + 4096) * 4)

__global__ __launch_bounds__(256) void attn_kernel()
{
    extern __shared__ float sm[];
    float* Qs  = sm;
    float* Kst = sm + 4096;
    float* Vs  = Kst + 64*65;
    float* Ps  = Vs + 4096;

    int tid = threadIdx.x;
    int tx = tid & 15, ty = tid >> 4;
    int bh = blockIdx.y;
    int q0 = blockIdx.x * 64;
    const float scale = 0.125f;
    int base = bh * NN * DD;

    #pragma unroll
    for (int s = 0; s < 4; s++) {
        int e = tid + 256*s;
        int r = e >> 4;
        int d = (e & 15) * 4;
        float4 v = make_float4(0.f, 0.f, 0.f, 0.f);
        if (q0 + r < NN) v = *(const float4*)&g_q[base + (q0 + r)*DD + d];
        v.x *= scale; v.y *= scale; v.z *= scale; v.w *= scale;
        *(float4*)&Qs[r*64 + d] = v;
    }

    float m_i[4], l_i[4], acc[4][4];
    #pragma unroll
    for (int i = 0; i < 4; i++) {
        m_i[i] = -1e30f; l_i[i] = 0.f;
        #pragma unroll
        for (int j = 0; j < 4; j++) acc[i][j] = 0.f;
    }

    for (int t0 = 0; t0 < NN; t0 += 64) {
        __syncthreads();

        #pragma unroll
        for (int s = 0; s < 4; s++) {
            int e = tid + 256*s;
            int c = e >> 4;
            int d = (e & 15) * 4;
            float4 kv = make_float4(0.f, 0.f, 0.f, 0.f);
            float4 vv = kv;
            if (t0 + c < NN) {
                kv = *(const float4*)&g_k[base + (t0 + c)*DD + d];
                vv = *(const float4*)&g_v[base + (t0 + c)*DD + d];
            }
            Kst[(d+0)*65 + c] = kv.x;
            Kst[(d+1)*65 + c] = kv.y;
            Kst[(d+2)*65 + c] = kv.z;
            Kst[(d+3)*65 + c] = kv.w;
            *(float4*)&Vs[c*64 + d] = vv;
        }
        __syncthreads();

        float s4[4][4];
        #pragma unroll
        for (int i = 0; i < 4; i++)
            #pragma unroll
            for (int j = 0; j < 4; j++) s4[i][j] = 0.f;

        #pragma unroll 16
        for (int kk = 0; kk < 64; kk++) {
            float qv[4], kvr[4];
            #pragma unroll
            for (int i = 0; i < 4; i++) qv[i] = Qs[(ty*4 + i)*64 + kk];
            #pragma unroll
            for (int j = 0; j < 4; j++) kvr[j] = Kst[kk*65 + tx*4 + j];
            #pragma unroll
            for (int i = 0; i < 4; i++)
                #pragma unroll
                for (int j = 0; j < 4; j++) s4[i][j] += qv[i] * kvr[j];
        }

        int cbase = t0 + tx*4;
        #pragma unroll
        for (int i = 0; i < 4; i++) {
            #pragma unroll
            for (int j = 0; j < 4; j++)
                if (cbase + j >= NN) s4[i][j] = -1e30f;
            float mloc = fmaxf(fmaxf(s4[i][0], s4[i][1]), fmaxf(s4[i][2], s4[i][3]));
            #pragma unroll
            for (int off = 8; off >= 1; off >>= 1)
                mloc = fmaxf(mloc, __shfl_xor_sync(0xffffffffu, mloc, off));
            float mnew = fmaxf(m_i[i], mloc);
            float corr = __expf(m_i[i] - mnew);
            m_i[i] = mnew;
            float p[4], ps = 0.f;
            #pragma unroll
            for (int j = 0; j < 4; j++) { p[j] = __expf(s4[i][j] - mnew); ps += p[j]; }
            #pragma unroll
            for (int off = 8; off >= 1; off >>= 1)
                ps += __shfl_xor_sync(0xffffffffu, ps, off);
            l_i[i] = l_i[i]*corr + ps;
            #pragma unroll
            for (int j = 0; j < 4; j++) acc[i][j] *= corr;
            *(float4*)&Ps[(ty*4 + i)*64 + tx*4] = make_float4(p[0], p[1], p[2], p[3]);
        }
        __syncthreads();

        #pragma unroll 8
        for (int c = 0; c < 64; c++) {
            float4 vv = *(const float4*)&Vs[c*64 + tx*4];
            #pragma unroll
            for (int i = 0; i < 4; i++) {
                float p = Ps[(ty*4 + i)*64 + c];
                acc[i][0] += p * vv.x;
                acc[i][1] += p * vv.y;
                acc[i][2] += p * vv.z;
                acc[i][3] += p * vv.w;
            }
        }
    }

    int b = bh / HH, h = bh % HH;
    #pragma unroll
    for (int i = 0; i < 4; i++) {
        int r = q0 + ty*4 + i;
        if (r < NN) {
            float inv = 1.f / l_i[i];
            float4 o = make_float4(acc[i][0]*inv, acc[i][1]*inv,
                                   acc[i][2]*inv, acc[i][3]*inv);
            *(float4*)&g_o[(b*NN + r)*CC + h*DD + tx*4] = o;
        }
    }
}

// ---------------- launch ----------------
extern "C" void kernel_launch(void* const* d_in, const int* in_sizes, int n_in,
                              void* d_out, int out_size)
{
    const float* x      = (const float*)d_in[0];
    const float* rope   = (const float*)d_in[1];
    const float* qkv_w  = (const float*)d_in[2];
    const float* q_bias = (const float*)d_in[3];
    const float* v_bias = (const float*)d_in[4];
    const float* proj_w = (const float*)d_in[5];
    const float* proj_b = (const float*)d_in[6];
    float* out = (float*)d_out;

    cudaFuncSetAttribute(attn_kernel,
                         cudaFuncAttributeMaxDynamicSharedMemorySize, ATTN_SMEM);

    const int MB = (MM + 127) / 128;   // 145

    // 1. QKV GEMM -> g_q, g_k, g_v (with bias)
    mma_gemm<0><<<dim3(QKV_N/128, MB), 256>>>(x, qkv_w, q_bias, v_bias, nullptr);

    // 2. RoPE in place on q, k
    int rtot = BB*HH*(NN-1)*(DD/2);
    rope_kernel<<<(rtot + 255)/256, 256>>>(rope);

    // 3. attention -> g_o
    attn_kernel<<<dim3(NTILES, BB*HH), 256, ATTN_SMEM>>>();

    // 4. output projection -> d_out
    mma_gemm<1><<<dim3(CC/128, MB), 256>>>(nullptr, proj_w, proj_b, nullptr, out);
}

// round 6
// speedup vs baseline: 2.6378x; 1.3525x over previous
#include <cuda_runtime.h>
#include <stdint.h>
#include <math.h>

#define BB 32
#define NN 577
#define CC 768
#define HH 12
#define DD 64
#define MM (BB*NN)      // 18464
#define KDIM 768
#define QKV_N 2304
#define NTILES ((NN + 63) / 64)   // 10

// ---------------- scratch ----------------
__device__ float g_q[BB*HH*NN*DD];   // [B,H,N,D]
__device__ float g_k[BB*HH*NN*DD];
__device__ float g_v[BB*HH*NN*DD];
__device__ float g_o[MM*CC];         // attention output, [B*N, C]

__device__ __forceinline__ float to_tf32(float x) {
    uint32_t u;
    asm("cvt.rna.tf32.f32 %0, %1;" : "=r"(u) : "f"(x));
    return __uint_as_float(u);
}

// bf16 helpers
__device__ __forceinline__ uint32_t f2bf(float x) {
    uint32_t u = __float_as_uint(x);
    return (u + 0x7FFFu + ((u >> 16) & 1u)) >> 16;
}
__device__ __forceinline__ float bf2f(uint32_t h) {
    return __uint_as_float(h << 16);
}
__device__ __forceinline__ uint32_t pack2(float a, float b) {
    return f2bf(a) | (f2bf(b) << 16);
}
// split (a,b) into bf16 hi pair + bf16 residual-lo pair
__device__ __forceinline__ void split2(float a, float b, uint32_t& hi, uint32_t& lo) {
    uint32_t ha = f2bf(a), hb = f2bf(b);
    hi = ha | (hb << 16);
    lo = pack2(a - bf2f(ha), b - bf2f(hb));
}

__device__ __forceinline__ void mma_bf16(float* c, const uint32_t* a, uint32_t b0, uint32_t b1) {
    asm volatile(
        "mma.sync.aligned.m16n8k16.row.col.f32.bf16.bf16.f32 "
        "{%0,%1,%2,%3},{%4,%5,%6,%7},{%8,%9},{%0,%1,%2,%3};"
        : "+f"(c[0]), "+f"(c[1]), "+f"(c[2]), "+f"(c[3])
        : "r"(a[0]), "r"(a[1]), "r"(a[2]), "r"(a[3]), "r"(b0), "r"(b1));
}

// ---------------- tf32 tensor-core GEMM (unchanged, proven) ----------------
#define SA 36

template<int MODE>
__global__ __launch_bounds__(256) void mma_gemm(
    const float* __restrict__ A_in, const float* __restrict__ W,
    const float* __restrict__ bias_q, const float* __restrict__ bias_v,
    float* __restrict__ out)
{
    __shared__ float As[128*SA];
    __shared__ float Bs[128*SA];

    const float* A = (MODE == 1) ? (const float*)g_o : A_in;

    const int tid  = threadIdx.x;
    const int lane = tid & 31;
    const int warp = tid >> 5;
    const int wm   = (warp >> 2) * 64;
    const int wn   = (warp & 3) * 32;
    const int r    = lane >> 2;
    const int cg   = lane & 3;

    const int m0 = blockIdx.y * 128;
    const int n0 = blockIdx.x * 128;

    const int sm_ = tid >> 1;
    const int skq = (tid & 1) * 16;

    float acc[4][4][4];
    #pragma unroll
    for (int i = 0; i < 4; i++)
        #pragma unroll
        for (int j = 0; j < 4; j++)
            #pragma unroll
            for (int q = 0; q < 4; q++) acc[i][j][q] = 0.f;

    float4 pa[4], pb[4];
    {
        int gm = m0 + sm_;
        #pragma unroll
        for (int s = 0; s < 4; s++) {
            pa[s] = (gm < MM) ? *(const float4*)&A[(size_t)gm*KDIM + skq + s*4]
                              : make_float4(0.f,0.f,0.f,0.f);
            pb[s] = *(const float4*)&W[(size_t)(n0 + sm_)*KDIM + skq + s*4];
        }
    }

    const int NK = KDIM / 32;
    for (int kt = 0; kt < NK; kt++) {
        #pragma unroll
        for (int s = 0; s < 4; s++) {
            float4 a = pa[s], b = pb[s];
            float* pA = &As[sm_*SA + skq + s*4];
            pA[0] = to_tf32(a.x); pA[1] = to_tf32(a.y);
            pA[2] = to_tf32(a.z); pA[3] = to_tf32(a.w);
            float* pB = &Bs[sm_*SA + skq + s*4];
            pB[0] = to_tf32(b.x); pB[1] = to_tf32(b.y);
            pB[2] = to_tf32(b.z); pB[3] = to_tf32(b.w);
        }
        __syncthreads();

        if (kt + 1 < NK) {
            int k0 = (kt + 1) * 32;
            int gm = m0 + sm_;
            #pragma unroll
            for (int s = 0; s < 4; s++) {
                pa[s] = (gm < MM) ? *(const float4*)&A[(size_t)gm*KDIM + k0 + skq + s*4]
                                  : make_float4(0.f,0.f,0.f,0.f);
                pb[s] = *(const float4*)&W[(size_t)(n0 + sm_)*KDIM + k0 + skq + s*4];
            }
        }

        #pragma unroll
        for (int kk = 0; kk < 32; kk += 8) {
            uint32_t af[4][4], bf[4][2];
            #pragma unroll
            for (int mt = 0; mt < 4; mt++) {
                const float* p = &As[(wm + mt*16 + r)*SA + kk + cg];
                af[mt][0] = __float_as_uint(p[0]);
                af[mt][1] = __float_as_uint(p[8*SA]);
                af[mt][2] = __float_as_uint(p[4]);
                af[mt][3] = __float_as_uint(p[8*SA + 4]);
            }
            #pragma unroll
            for (int nt = 0; nt < 4; nt++) {
                const float* p = &Bs[(wn + nt*8 + r)*SA + kk + cg];
                bf[nt][0] = __float_as_uint(p[0]);
                bf[nt][1] = __float_as_uint(p[4]);
            }
            #pragma unroll
            for (int mt = 0; mt < 4; mt++)
                #pragma unroll
                for (int nt = 0; nt < 4; nt++) {
                    asm volatile(
                        "mma.sync.aligned.m16n8k8.row.col.f32.tf32.tf32.f32 "
                        "{%0,%1,%2,%3},{%4,%5,%6,%7},{%8,%9},{%0,%1,%2,%3};"
                        : "+f"(acc[mt][nt][0]), "+f"(acc[mt][nt][1]),
                          "+f"(acc[mt][nt][2]), "+f"(acc[mt][nt][3])
                        : "r"(af[mt][0]), "r"(af[mt][1]),
                          "r"(af[mt][2]), "r"(af[mt][3]),
                          "r"(bf[nt][0]), "r"(bf[nt][1]));
                }
        }
        __syncthreads();
    }

    #pragma unroll
    for (int nt = 0; nt < 4; nt++) {
        int col = n0 + wn + nt*8 + 2*cg;
        if (MODE == 0) {
            int which = col / CC;
            int rem   = col - which*CC;
            int h     = rem >> 6;
            int d     = rem & 63;
            float b0 = (which == 0) ? bias_q[rem]   : (which == 2) ? bias_v[rem]   : 0.f;
            float b1 = (which == 0) ? bias_q[rem+1] : (which == 2) ? bias_v[rem+1] : 0.f;
            float* dst = (which == 0) ? g_q : (which == 1) ? g_k : g_v;
            #pragma unroll
            for (int mt = 0; mt < 4; mt++) {
                #pragma unroll
                for (int half = 0; half < 2; half++) {
                    int m = m0 + wm + mt*16 + r + half*8;
                    if (m < MM) {
                        int bb = m / NN, n = m - bb*NN;
                        float2 v = make_float2(acc[mt][nt][half*2]   + b0,
                                               acc[mt][nt][half*2+1] + b1);
                        *(float2*)&dst[(((size_t)bb*HH + h)*NN + n)*DD + d] = v;
                    }
                }
            }
        } else {
            float b0 = bias_q[col], b1 = bias_q[col+1];
            #pragma unroll
            for (int mt = 0; mt < 4; mt++) {
                #pragma unroll
                for (int half = 0; half < 2; half++) {
                    int m = m0 + wm + mt*16 + r + half*8;
                    if (m < MM) {
                        float2 v = make_float2(acc[mt][nt][half*2]   + b0,
                                               acc[mt][nt][half*2+1] + b1);
                        *(float2*)&out[(size_t)m*CC + col] = v;
                    }
                }
            }
        }
    }
}

// ---------------- RoPE ----------------
__global__ void rope_kernel(const float* __restrict__ rope)
{
    int idx = blockIdx.x * blockDim.x + threadIdx.x;
    const int total = BB*HH*(NN-1)*(DD/2);
    if (idx >= total) return;
    int pair = idx & 31;
    int rest = idx >> 5;
    int nr = rest % (NN-1);
    int bh = rest / (NN-1);
    int d0 = pair * 2;

    float s0 = rope[nr*2*DD + d0];
    float s1 = rope[nr*2*DD + d0 + 1];
    float c0 = rope[nr*2*DD + DD + d0];
    float c1 = rope[nr*2*DD + DD + d0 + 1];

    int base = (bh*NN + (nr + 1))*DD + d0;
    float2 q = *(float2*)&g_q[base];
    float2 k = *(float2*)&g_k[base];
    *(float2*)&g_q[base] = make_float2(q.x*c0 - q.y*s0, q.y*c1 + q.x*s1);
    *(float2*)&g_k[base] = make_float2(k.x*c0 - k.y*s0, k.y*c1 + k.x*s1);
}

// ---------------- Tensor-core flash attention (bf16x3, max-free softmax) ----
#define AT_STR 36                         // u32 stride (= 72 bf16)
#define AT_U32 (6*64*AT_STR)              // 13824 u32
#define ATTN2_SMEM ((AT_U32 + 128) * 4)   // 55808 B

__global__ __launch_bounds__(256) void attn_mma_kernel()
{
    extern __shared__ uint32_t smu[];
    uint32_t* Kh = smu;
    uint32_t* Kl = Kh + 64*AT_STR;
    uint32_t* Vh = Kl + 64*AT_STR;
    uint32_t* Vl = Vh + 64*AT_STR;
    uint32_t* Ph = Vl + 64*AT_STR;
    uint32_t* Pl = Ph + 64*AT_STR;
    float*   lsum = (float*)(smu + AT_U32);    // [2][64]

    const int tid  = threadIdx.x;
    const int lane = tid & 31;
    const int wid  = tid >> 5;
    const int r    = lane >> 2;    // 0..7
    const int cg   = lane & 3;     // 0..3
    const int mw   = wid >> 1;     // 0..3
    const int nw   = wid & 1;      // 0..1

    const int bh   = blockIdx.y;
    const int q0   = blockIdx.x * 64;
    const int base = bh * NN * DD;         // element offset of this head
    const float scale = 0.125f;

    // ---- Q fragments (persistent, bf16 hi/lo), rows mw*16 + r / +8 ----
    uint32_t qh[4][4], ql[4][4];   // [kstep][a-reg]
    {
        int row0 = q0 + mw*16 + r;      if (row0 >= NN) row0 = 0;
        int row1 = q0 + mw*16 + r + 8;  if (row1 >= NN) row1 = 0;
        #pragma unroll
        for (int ks = 0; ks < 4; ks++) {
            float2 v;
            v = *(const float2*)&g_q[base + row0*DD + ks*16 + 2*cg];
            split2(v.x*scale, v.y*scale, qh[ks][0], ql[ks][0]);
            v = *(const float2*)&g_q[base + row1*DD + ks*16 + 2*cg];
            split2(v.x*scale, v.y*scale, qh[ks][1], ql[ks][1]);
            v = *(const float2*)&g_q[base + row0*DD + ks*16 + 2*cg + 8];
            split2(v.x*scale, v.y*scale, qh[ks][2], ql[ks][2]);
            v = *(const float2*)&g_q[base + row1*DD + ks*16 + 2*cg + 8];
            split2(v.x*scale, v.y*scale, qh[ks][3], ql[ks][3]);
        }
    }

    float o[4][4];                 // [dtile][c-frag]
    #pragma unroll
    for (int i = 0; i < 4; i++)
        #pragma unroll
        for (int j = 0; j < 4; j++) o[i][j] = 0.f;
    float lp0 = 0.f, lp1 = 0.f;    // row-sum partials (rows r, r+8)

    for (int t0 = 0; t0 < NN; t0 += 64) {
        __syncthreads();

        // ---- stage K,V tile as bf16 hi/lo (clamped rows; masked later) ----
        #pragma unroll
        for (int s = 0; s < 4; s++) {
            int f4 = tid + 256*s;          // 0..1023
            int c  = f4 >> 4;
            int dq = f4 & 15;              // float4 index in row
            int gr = t0 + c; if (gr >= NN) gr = NN - 1;
            float4 kv = *(const float4*)&g_k[base + gr*DD + dq*4];
            float4 vv = *(const float4*)&g_v[base + gr*DD + dq*4];
            uint32_t h0, l0, h1, l1;
            split2(kv.x, kv.y, h0, l0); split2(kv.z, kv.w, h1, l1);
            Kh[c*AT_STR + dq*2]     = h0;  Kh[c*AT_STR + dq*2 + 1] = h1;
            Kl[c*AT_STR + dq*2]     = l0;  Kl[c*AT_STR + dq*2 + 1] = l1;
            split2(vv.x, vv.y, h0, l0); split2(vv.z, vv.w, h1, l1);
            Vh[c*AT_STR + dq*2]     = h0;  Vh[c*AT_STR + dq*2 + 1] = h1;
            Vl[c*AT_STR + dq*2]     = l0;  Vl[c*AT_STR + dq*2 + 1] = l1;
        }
        __syncthreads();

        // ---- scores: S[m16][n32] per warp, bf16x3 ----
        float s4[4][4];
        #pragma unroll
        for (int nt = 0; nt < 4; nt++)
            #pragma unroll
            for (int j = 0; j < 4; j++) s4[nt][j] = 0.f;

        #pragma unroll
        for (int nt = 0; nt < 4; nt++) {
            int colr = nw*32 + nt*8 + r;          // B n-index
            #pragma unroll
            for (int ks = 0; ks < 4; ks++) {
                uint32_t bh0 = Kh[colr*AT_STR + ks*8 + cg];
                uint32_t bh1 = Kh[colr*AT_STR + ks*8 + cg + 4];
                uint32_t bl0 = Kl[colr*AT_STR + ks*8 + cg];
                uint32_t bl1 = Kl[colr*AT_STR + ks*8 + cg + 4];
                mma_bf16(s4[nt], qh[ks], bh0, bh1);
                mma_bf16(s4[nt], qh[ks], bl0, bl1);
                mma_bf16(s4[nt], ql[ks], bh0, bh1);
            }
        }

        // ---- exp (max-free), mask, write P hi/lo, accumulate row sums ----
        #pragma unroll
        for (int nt = 0; nt < 4; nt++) {
            int c01 = t0 + nw*32 + nt*8 + 2*cg;
            float p0 = (c01     < NN) ? __expf(s4[nt][0]) : 0.f;
            float p1 = (c01 + 1 < NN) ? __expf(s4[nt][1]) : 0.f;
            float p2 = (c01     < NN) ? __expf(s4[nt][2]) : 0.f;
            float p3 = (c01 + 1 < NN) ? __expf(s4[nt][3]) : 0.f;
            lp0 += p0 + p1;
            lp1 += p2 + p3;
            uint32_t hi, lo;
            int idx0 = (mw*16 + r)*AT_STR + nw*16 + nt*4 + cg;
            split2(p0, p1, hi, lo);  Ph[idx0] = hi;  Pl[idx0] = lo;
            int idx1 = idx0 + 8*AT_STR;
            split2(p2, p3, hi, lo);  Ph[idx1] = hi;  Pl[idx1] = lo;
        }
        __syncthreads();

        // ---- o += P @ V (bf16x3) ----
        uint32_t ah[4][4], al[4][4];
        #pragma unroll
        for (int ks = 0; ks < 4; ks++) {
            int i0 = (mw*16 + r)*AT_STR + ks*8 + cg;
            ah[ks][0] = Ph[i0];             al[ks][0] = Pl[i0];
            ah[ks][1] = Ph[i0 + 8*AT_STR];  al[ks][1] = Pl[i0 + 8*AT_STR];
            ah[ks][2] = Ph[i0 + 4];         al[ks][2] = Pl[i0 + 4];
            ah[ks][3] = Ph[i0 + 4 + 8*AT_STR]; al[ks][3] = Pl[i0 + 4 + 8*AT_STR];
        }
        const uint16_t* Vh16 = (const uint16_t*)Vh;
        const uint16_t* Vl16 = (const uint16_t*)Vl;
        #pragma unroll
        for (int dt = 0; dt < 4; dt++) {
            int d = nw*32 + dt*8 + r;           // B n-index
            #pragma unroll
            for (int ks = 0; ks < 4; ks++) {
                int c0 = ks*16 + 2*cg;
                uint32_t bh0 = (uint32_t)Vh16[c0*2*AT_STR + d]
                             | ((uint32_t)Vh16[(c0+1)*2*AT_STR + d] << 16);
                uint32_t bh1 = (uint32_t)Vh16[(c0+8)*2*AT_STR + d]
                             | ((uint32_t)Vh16[(c0+9)*2*AT_STR + d] << 16);
                uint32_t bl0 = (uint32_t)Vl16[c0*2*AT_STR + d]
                             | ((uint32_t)Vl16[(c0+1)*2*AT_STR + d] << 16);
                uint32_t bl1 = (uint32_t)Vl16[(c0+8)*2*AT_STR + d]
                             | ((uint32_t)Vl16[(c0+9)*2*AT_STR + d] << 16);
                mma_bf16(o[dt], ah[ks], bh0, bh1);
                mma_bf16(o[dt], ah[ks], bl0, bl1);
                mma_bf16(o[dt], al[ks], bh0, bh1);
            }
        }
    }

    // ---- reduce row sums, combine n-warp halves via smem ----
    lp0 += __shfl_xor_sync(0xffffffffu, lp0, 1);
    lp0 += __shfl_xor_sync(0xffffffffu, lp0, 2);
    lp1 += __shfl_xor_sync(0xffffffffu, lp1, 1);
    lp1 += __shfl_xor_sync(0xffffffffu, lp1, 2);
    if (cg == 0) {
        lsum[nw*64 + mw*16 + r]     = lp0;
        lsum[nw*64 + mw*16 + r + 8] = lp1;
    }
    __syncthreads();

    const int b = bh / HH, h = bh % HH;
    const int lrow0 = mw*16 + r, lrow1 = lrow0 + 8;
    const float inv0 = 1.f / (lsum[lrow0] + lsum[64 + lrow0]);
    const float inv1 = 1.f / (lsum[lrow1] + lsum[64 + lrow1]);

    #pragma unroll
    for (int dt = 0; dt < 4; dt++) {
        int d = nw*32 + dt*8 + 2*cg;
        if (q0 + lrow0 < NN)
            *(float2*)&g_o[((size_t)(b*NN + q0 + lrow0))*CC + h*DD + d] =
                make_float2(o[dt][0]*inv0, o[dt][1]*inv0);
        if (q0 + lrow1 < NN)
            *(float2*)&g_o[((size_t)(b*NN + q0 + lrow1))*CC + h*DD + d] =
                make_float2(o[dt][2]*inv1, o[dt][3]*inv1);
    }
}

// ---------------- launch ----------------
extern "C" void kernel_launch(void* const* d_in, const int* in_sizes, int n_in,
                              void* d_out, int out_size)
{
    const float* x      = (const float*)d_in[0];
    const float* rope   = (const float*)d_in[1];
    const float* qkv_w  = (const float*)d_in[2];
    const float* q_bias = (const float*)d_in[3];
    const float* v_bias = (const float*)d_in[4];
    const float* proj_w = (const float*)d_in[5];
    const float* proj_b = (const float*)d_in[6];
    float* out = (float*)d_out;

    cudaFuncSetAttribute(attn_mma_kernel,
                         cudaFuncAttributeMaxDynamicSharedMemorySize, ATTN2_SMEM);

    const int MB = (MM + 127) / 128;

    mma_gemm<0><<<dim3(QKV_N/128, MB), 256>>>(x, qkv_w, q_bias, v_bias, nullptr);

    int rtot = BB*HH*(NN-1)*(DD/2);
    rope_kernel<<<(rtot + 255)/256, 256>>>(rope);

    attn_mma_kernel<<<dim3(NTILES, BB*HH), 256, ATTN2_SMEM>>>();

    mma_gemm<1><<<dim3(CC/128, MB), 256>>>(nullptr, proj_w, proj_b, nullptr, out);
}

// round 7
// speedup vs baseline: 3.4361x; 1.3026x over previous
#include <cuda_runtime.h>
#include <stdint.h>
#include <math.h>

#define BB 32
#define NN 577
#define CC 768
#define HH 12
#define DD 64
#define MM (BB*NN)      // 18464
#define KDIM 768
#define QKV_N 2304
#define NTILES ((NN + 63) / 64)   // 10

// ---------------- scratch ----------------
__device__ float g_q[BB*HH*NN*DD];   // [B,H,N,D]
__device__ float g_k[BB*HH*NN*DD];
__device__ float g_v[BB*HH*NN*DD];
__device__ float g_o[MM*CC];         // attention output (tf32-rounded), [B*N, C]
__device__ float g_xr[MM*KDIM];      // x, tf32-rounded
__device__ float g_wq[QKV_N*KDIM];   // qkv_w, tf32-rounded
__device__ float g_wp[CC*KDIM];      // proj_w, tf32-rounded

__device__ __forceinline__ float to_tf32(float x) {
    uint32_t u;
    asm("cvt.rna.tf32.f32 %0, %1;" : "=r"(u) : "f"(x));
    return __uint_as_float(u);
}

// bf16 helpers
__device__ __forceinline__ uint32_t f2bf(float x) {
    uint32_t u = __float_as_uint(x);
    return (u + 0x7FFFu + ((u >> 16) & 1u)) >> 16;
}
__device__ __forceinline__ float bf2f(uint32_t h) {
    return __uint_as_float(h << 16);
}
__device__ __forceinline__ uint32_t pack2(float a, float b) {
    return f2bf(a) | (f2bf(b) << 16);
}
__device__ __forceinline__ void split2(float a, float b, uint32_t& hi, uint32_t& lo) {
    uint32_t ha = f2bf(a), hb = f2bf(b);
    hi = ha | (hb << 16);
    lo = pack2(a - bf2f(ha), b - bf2f(hb));
}

__device__ __forceinline__ void mma_bf16(float* c, const uint32_t* a, uint32_t b0, uint32_t b1) {
    asm volatile(
        "mma.sync.aligned.m16n8k16.row.col.f32.bf16.bf16.f32 "
        "{%0,%1,%2,%3},{%4,%5,%6,%7},{%8,%9},{%0,%1,%2,%3};"
        : "+f"(c[0]), "+f"(c[1]), "+f"(c[2]), "+f"(c[3])
        : "r"(a[0]), "r"(a[1]), "r"(a[2]), "r"(a[3]), "r"(b0), "r"(b1));
}

__device__ __forceinline__ void cp16(uint32_t dst, const float* src, bool pred) {
    int sz = pred ? 16 : 0;
    asm volatile("cp.async.cg.shared.global [%0], [%1], 16, %2;"
                 :: "r"(dst), "l"(src), "r"(sz));
}

// ---------------- tf32 conversion (elementwise, float4) ----------------
__global__ void cvt_tf32_kernel(const float* __restrict__ in, float* __restrict__ out, int n4)
{
    int i = blockIdx.x * blockDim.x + threadIdx.x;
    if (i < n4) {
        float4 v = ((const float4*)in)[i];
        v.x = to_tf32(v.x); v.y = to_tf32(v.y);
        v.z = to_tf32(v.z); v.w = to_tf32(v.w);
        ((float4*)out)[i] = v;
    }
}

// ---------------- tf32 GEMM with cp.async double buffering ----------------
// C[M, Nout] = A[M,K] * W[Nout,K]^T. Tile 128x128x32, 8 warps (2m x 4n).
// Operands pre-rounded to tf32. smem: 2 stages x (A 16KB + B 16KB), XOR swizzle.
#define GEMM_SMEM (4 * 128 * 32 * 4)   // 65536 B

template<int MODE>
__global__ __launch_bounds__(256) void mma_gemm(
    const float* __restrict__ Aop, const float* __restrict__ Wop,
    const float* __restrict__ bias_q, const float* __restrict__ bias_v,
    float* __restrict__ out)
{
    extern __shared__ float smg[];
    float* As = smg;                // [2][128*32]
    float* Bs = smg + 2*128*32;

    const int tid  = threadIdx.x;
    const int lane = tid & 31;
    const int warp = tid >> 5;
    const int wm   = (warp >> 2) * 64;
    const int wn   = (warp & 3) * 32;
    const int r    = lane >> 2;
    const int cg   = lane & 3;

    const int m0 = blockIdx.y * 128;
    const int n0 = blockIdx.x * 128;

    uint32_t asu = (uint32_t)__cvta_generic_to_shared(As);
    uint32_t bsu = (uint32_t)__cvta_generic_to_shared(Bs);

    // staging: each thread copies 4 x 16B per matrix
    const int srow = tid >> 3;          // 0..31 (+32*i)
    const int sg   = tid & 7;           // 16B chunk in row

    float acc[4][4][4];
    #pragma unroll
    for (int i = 0; i < 4; i++)
        #pragma unroll
        for (int j = 0; j < 4; j++)
            #pragma unroll
            for (int q = 0; q < 4; q++) acc[i][j][q] = 0.f;

    const int NK = KDIM / 32;   // 24

    // issue one k-chunk into stage s
    auto issue = [&](int kt, int s) {
        int k0 = kt * 32;
        #pragma unroll
        for (int i = 0; i < 4; i++) {
            int row = srow + 32*i;
            int sw  = ((sg ^ (row & 7)) << 2);
            uint32_t off = (uint32_t)((s*4096 + row*32 + sw) << 2);
            cp16(asu + off, &Aop[(size_t)(m0+row)*KDIM + k0 + sg*4], (m0+row) < MM);
            cp16(bsu + off, &Wop[(size_t)(n0+row)*KDIM + k0 + sg*4], true);
        }
    };

    issue(0, 0);
    asm volatile("cp.async.commit_group;");

    for (int kt = 0; kt < NK; kt++) {
        const int s = kt & 1;
        if (kt + 1 < NK) {
            issue(kt + 1, (kt + 1) & 1);
            asm volatile("cp.async.commit_group;");
            asm volatile("cp.async.wait_group 1;");
        } else {
            asm volatile("cp.async.wait_group 0;");
        }
        __syncthreads();

        const float* Ab = As + s*4096;
        const float* Bb = Bs + s*4096;

        #pragma unroll
        for (int kk = 0; kk < 32; kk += 8) {
            const int g0 = kk >> 2;
            const int c0 = ((g0 ^ r) << 2) + cg;
            const int c1 = (((g0 + 1) ^ r) << 2) + cg;
            uint32_t af[4][4], bf[4][2];
            #pragma unroll
            for (int mt = 0; mt < 4; mt++) {
                const float* p = &Ab[(wm + mt*16 + r)*32];
                af[mt][0] = __float_as_uint(p[c0]);
                af[mt][1] = __float_as_uint(p[8*32 + c0]);
                af[mt][2] = __float_as_uint(p[c1]);
                af[mt][3] = __float_as_uint(p[8*32 + c1]);
            }
            #pragma unroll
            for (int nt = 0; nt < 4; nt++) {
                const float* p = &Bb[(wn + nt*8 + r)*32];
                bf[nt][0] = __float_as_uint(p[c0]);
                bf[nt][1] = __float_as_uint(p[c1]);
            }
            #pragma unroll
            for (int mt = 0; mt < 4; mt++)
                #pragma unroll
                for (int nt = 0; nt < 4; nt++) {
                    asm volatile(
                        "mma.sync.aligned.m16n8k8.row.col.f32.tf32.tf32.f32 "
                        "{%0,%1,%2,%3},{%4,%5,%6,%7},{%8,%9},{%0,%1,%2,%3};"
                        : "+f"(acc[mt][nt][0]), "+f"(acc[mt][nt][1]),
                          "+f"(acc[mt][nt][2]), "+f"(acc[mt][nt][3])
                        : "r"(af[mt][0]), "r"(af[mt][1]),
                          "r"(af[mt][2]), "r"(af[mt][3]),
                          "r"(bf[nt][0]), "r"(bf[nt][1]));
                }
        }
        __syncthreads();
    }

    // ---------------- epilogue ----------------
    #pragma unroll
    for (int nt = 0; nt < 4; nt++) {
        int col = n0 + wn + nt*8 + 2*cg;
        if (MODE == 0) {
            int which = col / CC;
            int rem   = col - which*CC;
            int h     = rem >> 6;
            int d     = rem & 63;
            float b0 = (which == 0) ? bias_q[rem]   : (which == 2) ? bias_v[rem]   : 0.f;
            float b1 = (which == 0) ? bias_q[rem+1] : (which == 2) ? bias_v[rem+1] : 0.f;
            float* dst = (which == 0) ? g_q : (which == 1) ? g_k : g_v;
            #pragma unroll
            for (int mt = 0; mt < 4; mt++) {
                #pragma unroll
                for (int half = 0; half < 2; half++) {
                    int m = m0 + wm + mt*16 + r + half*8;
                    if (m < MM) {
                        int bb = m / NN, n = m - bb*NN;
                        float2 v = make_float2(acc[mt][nt][half*2]   + b0,
                                               acc[mt][nt][half*2+1] + b1);
                        *(float2*)&dst[(((size_t)bb*HH + h)*NN + n)*DD + d] = v;
                    }
                }
            }
        } else {
            float b0 = bias_q[col], b1 = bias_q[col+1];
            #pragma unroll
            for (int mt = 0; mt < 4; mt++) {
                #pragma unroll
                for (int half = 0; half < 2; half++) {
                    int m = m0 + wm + mt*16 + r + half*8;
                    if (m < MM) {
                        float2 v = make_float2(acc[mt][nt][half*2]   + b0,
                                               acc[mt][nt][half*2+1] + b1);
                        *(float2*)&out[(size_t)m*CC + col] = v;
                    }
                }
            }
        }
    }
}

// ---------------- RoPE ----------------
__global__ void rope_kernel(const float* __restrict__ rope)
{
    int idx = blockIdx.x * blockDim.x + threadIdx.x;
    const int total = BB*HH*(NN-1)*(DD/2);
    if (idx >= total) return;
    int pair = idx & 31;
    int rest = idx >> 5;
    int nr = rest % (NN-1);
    int bh = rest / (NN-1);
    int d0 = pair * 2;

    float s0 = rope[nr*2*DD + d0];
    float s1 = rope[nr*2*DD + d0 + 1];
    float c0 = rope[nr*2*DD + DD + d0];
    float c1 = rope[nr*2*DD + DD + d0 + 1];

    int base = (bh*NN + (nr + 1))*DD + d0;
    float2 q = *(float2*)&g_q[base];
    float2 k = *(float2*)&g_k[base];
    *(float2*)&g_q[base] = make_float2(q.x*c0 - q.y*s0, q.y*c1 + q.x*s1);
    *(float2*)&g_k[base] = make_float2(k.x*c0 - k.y*s0, k.y*c1 + k.x*s1);
}

// ---------------- Tensor-core flash attention (bf16x3, max-free softmax) ----
#define AT_STR 36                         // u32 stride (= 72 bf16)
#define AT_U32 (6*64*AT_STR)              // 13824 u32
#define ATTN2_SMEM ((AT_U32 + 128) * 4)   // 55808 B

__global__ __launch_bounds__(256) void attn_mma_kernel()
{
    extern __shared__ uint32_t smu[];
    uint32_t* Kh = smu;
    uint32_t* Kl = Kh + 64*AT_STR;
    uint32_t* Vh = Kl + 64*AT_STR;
    uint32_t* Vl = Vh + 64*AT_STR;
    uint32_t* Ph = Vl + 64*AT_STR;
    uint32_t* Pl = Ph + 64*AT_STR;
    float*   lsum = (float*)(smu + AT_U32);    // [2][64]

    const int tid  = threadIdx.x;
    const int lane = tid & 31;
    const int wid  = tid >> 5;
    const int r    = lane >> 2;
    const int cg   = lane & 3;
    const int mw   = wid >> 1;
    const int nw   = wid & 1;

    const int bh   = blockIdx.y;
    const int q0   = blockIdx.x * 64;
    const int base = bh * NN * DD;
    const float scale = 0.125f;

    uint32_t qh[4][4], ql[4][4];
    {
        int row0 = q0 + mw*16 + r;      if (row0 >= NN) row0 = 0;
        int row1 = q0 + mw*16 + r + 8;  if (row1 >= NN) row1 = 0;
        #pragma unroll
        for (int ks = 0; ks < 4; ks++) {
            float2 v;
            v = *(const float2*)&g_q[base + row0*DD + ks*16 + 2*cg];
            split2(v.x*scale, v.y*scale, qh[ks][0], ql[ks][0]);
            v = *(const float2*)&g_q[base + row1*DD + ks*16 + 2*cg];
            split2(v.x*scale, v.y*scale, qh[ks][1], ql[ks][1]);
            v = *(const float2*)&g_q[base + row0*DD + ks*16 + 2*cg + 8];
            split2(v.x*scale, v.y*scale, qh[ks][2], ql[ks][2]);
            v = *(const float2*)&g_q[base + row1*DD + ks*16 + 2*cg + 8];
            split2(v.x*scale, v.y*scale, qh[ks][3], ql[ks][3]);
        }
    }

    float o[4][4];
    #pragma unroll
    for (int i = 0; i < 4; i++)
        #pragma unroll
        for (int j = 0; j < 4; j++) o[i][j] = 0.f;
    float lp0 = 0.f, lp1 = 0.f;

    for (int t0 = 0; t0 < NN; t0 += 64) {
        __syncthreads();

        #pragma unroll
        for (int s = 0; s < 4; s++) {
            int f4 = tid + 256*s;
            int c  = f4 >> 4;
            int dq = f4 & 15;
            int gr = t0 + c; if (gr >= NN) gr = NN - 1;
            float4 kv = *(const float4*)&g_k[base + gr*DD + dq*4];
            float4 vv = *(const float4*)&g_v[base + gr*DD + dq*4];
            uint32_t h0, l0, h1, l1;
            split2(kv.x, kv.y, h0, l0); split2(kv.z, kv.w, h1, l1);
            Kh[c*AT_STR + dq*2]     = h0;  Kh[c*AT_STR + dq*2 + 1] = h1;
            Kl[c*AT_STR + dq*2]     = l0;  Kl[c*AT_STR + dq*2 + 1] = l1;
            split2(vv.x, vv.y, h0, l0); split2(vv.z, vv.w, h1, l1);
            Vh[c*AT_STR + dq*2]     = h0;  Vh[c*AT_STR + dq*2 + 1] = h1;
            Vl[c*AT_STR + dq*2]     = l0;  Vl[c*AT_STR + dq*2 + 1] = l1;
        }
        __syncthreads();

        float s4[4][4];
        #pragma unroll
        for (int nt = 0; nt < 4; nt++)
            #pragma unroll
            for (int j = 0; j < 4; j++) s4[nt][j] = 0.f;

        #pragma unroll
        for (int nt = 0; nt < 4; nt++) {
            int colr = nw*32 + nt*8 + r;
            #pragma unroll
            for (int ks = 0; ks < 4; ks++) {
                uint32_t bh0 = Kh[colr*AT_STR + ks*8 + cg];
                uint32_t bh1 = Kh[colr*AT_STR + ks*8 + cg + 4];
                uint32_t bl0 = Kl[colr*AT_STR + ks*8 + cg];
                uint32_t bl1 = Kl[colr*AT_STR + ks*8 + cg + 4];
                mma_bf16(s4[nt], qh[ks], bh0, bh1);
                mma_bf16(s4[nt], qh[ks], bl0, bl1);
                mma_bf16(s4[nt], ql[ks], bh0, bh1);
            }
        }

        #pragma unroll
        for (int nt = 0; nt < 4; nt++) {
            int c01 = t0 + nw*32 + nt*8 + 2*cg;
            float p0 = (c01     < NN) ? __expf(s4[nt][0]) : 0.f;
            float p1 = (c01 + 1 < NN) ? __expf(s4[nt][1]) : 0.f;
            float p2 = (c01     < NN) ? __expf(s4[nt][2]) : 0.f;
            float p3 = (c01 + 1 < NN) ? __expf(s4[nt][3]) : 0.f;
            lp0 += p0 + p1;
            lp1 += p2 + p3;
            uint32_t hi, lo;
            int idx0 = (mw*16 + r)*AT_STR + nw*16 + nt*4 + cg;
            split2(p0, p1, hi, lo);  Ph[idx0] = hi;  Pl[idx0] = lo;
            int idx1 = idx0 + 8*AT_STR;
            split2(p2, p3, hi, lo);  Ph[idx1] = hi;  Pl[idx1] = lo;
        }
        __syncthreads();

        uint32_t ah[4][4], al[4][4];
        #pragma unroll
        for (int ks = 0; ks < 4; ks++) {
            int i0 = (mw*16 + r)*AT_STR + ks*8 + cg;
            ah[ks][0] = Ph[i0];             al[ks][0] = Pl[i0];
            ah[ks][1] = Ph[i0 + 8*AT_STR];  al[ks][1] = Pl[i0 + 8*AT_STR];
            ah[ks][2] = Ph[i0 + 4];         al[ks][2] = Pl[i0 + 4];
            ah[ks][3] = Ph[i0 + 4 + 8*AT_STR]; al[ks][3] = Pl[i0 + 4 + 8*AT_STR];
        }
        const uint16_t* Vh16 = (const uint16_t*)Vh;
        const uint16_t* Vl16 = (const uint16_t*)Vl;
        #pragma unroll
        for (int dt = 0; dt < 4; dt++) {
            int d = nw*32 + dt*8 + r;
            #pragma unroll
            for (int ks = 0; ks < 4; ks++) {
                int c0 = ks*16 + 2*cg;
                uint32_t bh0 = (uint32_t)Vh16[c0*2*AT_STR + d]
                             | ((uint32_t)Vh16[(c0+1)*2*AT_STR + d] << 16);
                uint32_t bh1 = (uint32_t)Vh16[(c0+8)*2*AT_STR + d]
                             | ((uint32_t)Vh16[(c0+9)*2*AT_STR + d] << 16);
                uint32_t bl0 = (uint32_t)Vl16[c0*2*AT_STR + d]
                             | ((uint32_t)Vl16[(c0+1)*2*AT_STR + d] << 16);
                uint32_t bl1 = (uint32_t)Vl16[(c0+8)*2*AT_STR + d]
                             | ((uint32_t)Vl16[(c0+9)*2*AT_STR + d] << 16);
                mma_bf16(o[dt], ah[ks], bh0, bh1);
                mma_bf16(o[dt], ah[ks], bl0, bl1);
                mma_bf16(o[dt], al[ks], bh0, bh1);
            }
        }
    }

    lp0 += __shfl_xor_sync(0xffffffffu, lp0, 1);
    lp0 += __shfl_xor_sync(0xffffffffu, lp0, 2);
    lp1 += __shfl_xor_sync(0xffffffffu, lp1, 1);
    lp1 += __shfl_xor_sync(0xffffffffu, lp1, 2);
    if (cg == 0) {
        lsum[nw*64 + mw*16 + r]     = lp0;
        lsum[nw*64 + mw*16 + r + 8] = lp1;
    }
    __syncthreads();

    const int b = bh / HH, h = bh % HH;
    const int lrow0 = mw*16 + r, lrow1 = lrow0 + 8;
    const float inv0 = 1.f / (lsum[lrow0] + lsum[64 + lrow0]);
    const float inv1 = 1.f / (lsum[lrow1] + lsum[64 + lrow1]);

    // store tf32-rounded so proj GEMM can consume directly (same numerics as before)
    #pragma unroll
    for (int dt = 0; dt < 4; dt++) {
        int d = nw*32 + dt*8 + 2*cg;
        if (q0 + lrow0 < NN)
            *(float2*)&g_o[((size_t)(b*NN + q0 + lrow0))*CC + h*DD + d] =
                make_float2(to_tf32(o[dt][0]*inv0), to_tf32(o[dt][1]*inv0));
        if (q0 + lrow1 < NN)
            *(float2*)&g_o[((size_t)(b*NN + q0 + lrow1))*CC + h*DD + d] =
                make_float2(to_tf32(o[dt][2]*inv1), to_tf32(o[dt][3]*inv1));
    }
}

// ---------------- launch ----------------
extern "C" void kernel_launch(void* const* d_in, const int* in_sizes, int n_in,
                              void* d_out, int out_size)
{
    const float* x      = (const float*)d_in[0];
    const float* rope   = (const float*)d_in[1];
    const float* qkv_w  = (const float*)d_in[2];
    const float* q_bias = (const float*)d_in[3];
    const float* v_bias = (const float*)d_in[4];
    const float* proj_w = (const float*)d_in[5];
    const float* proj_b = (const float*)d_in[6];
    float* out = (float*)d_out;

    cudaFuncSetAttribute(attn_mma_kernel,
                         cudaFuncAttributeMaxDynamicSharedMemorySize, ATTN2_SMEM);
    cudaFuncSetAttribute(mma_gemm<0>,
                         cudaFuncAttributeMaxDynamicSharedMemorySize, GEMM_SMEM);
    cudaFuncSetAttribute(mma_gemm<1>,
                         cudaFuncAttributeMaxDynamicSharedMemorySize, GEMM_SMEM);

    float* xr; cudaGetSymbolAddress((void**)&xr, g_xr);
    float* wq; cudaGetSymbolAddress((void**)&wq, g_wq);
    float* wp; cudaGetSymbolAddress((void**)&wp, g_wp);

    // 0. pre-round operands to tf32
    cvt_tf32_kernel<<<(MM*KDIM/4 + 255)/256, 256>>>(x, xr, MM*KDIM/4);
    cvt_tf32_kernel<<<(QKV_N*KDIM/4 + 255)/256, 256>>>(qkv_w, wq, QKV_N*KDIM/4);
    cvt_tf32_kernel<<<(CC*KDIM/4 + 255)/256, 256>>>(proj_w, wp, CC*KDIM/4);

    const int MB = (MM + 127) / 128;

    // 1. QKV GEMM -> g_q, g_k, g_v
    mma_gemm<0><<<dim3(QKV_N/128, MB), 256, GEMM_SMEM>>>(xr, wq, q_bias, v_bias, nullptr);

    // 2. RoPE
    int rtot = BB*HH*(NN-1)*(DD/2);
    rope_kernel<<<(rtot + 255)/256, 256>>>(rope);

    // 3. attention -> g_o (tf32-rounded)
    attn_mma_kernel<<<dim3(NTILES, BB*HH), 256, ATTN2_SMEM>>>();

    // 4. output projection -> d_out
    float* go; cudaGetSymbolAddress((void**)&go, g_o);
    mma_gemm<1><<<dim3(CC/128, MB), 256, GEMM_SMEM>>>(go, wp, proj_b, nullptr, out);
}

// round 8
// speedup vs baseline: 3.8136x; 1.1099x over previous
#include <cuda_runtime.h>
#include <stdint.h>
#include <math.h>

#define BB 32
#define NN 577
#define CC 768
#define HH 12
#define DD 64
#define MM (BB*NN)      // 18464
#define KDIM 768
#define QKV_N 2304

// ---------------- scratch ----------------
__device__ float g_q[BB*HH*NN*DD];   // [B,H,N,D]
__device__ float g_k[BB*HH*NN*DD];
__device__ float g_v[BB*HH*NN*DD];
__device__ float g_o[MM*CC];         // attention output (tf32-rounded), [B*N, C]
__device__ float g_xr[MM*KDIM];      // x, tf32-rounded
__device__ float g_wq[QKV_N*KDIM];   // qkv_w, tf32-rounded
__device__ float g_wp[CC*KDIM];      // proj_w, tf32-rounded

__device__ __forceinline__ float to_tf32(float x) {
    uint32_t u;
    asm("cvt.rna.tf32.f32 %0, %1;" : "=r"(u) : "f"(x));
    return __uint_as_float(u);
}

// bf16 helpers
__device__ __forceinline__ uint32_t f2bf(float x) {
    uint32_t u = __float_as_uint(x);
    return (u + 0x7FFFu + ((u >> 16) & 1u)) >> 16;
}
__device__ __forceinline__ float bf2f(uint32_t h) {
    return __uint_as_float(h << 16);
}
__device__ __forceinline__ uint32_t pack2(float a, float b) {
    return f2bf(a) | (f2bf(b) << 16);
}
__device__ __forceinline__ void split2(float a, float b, uint32_t& hi, uint32_t& lo) {
    uint32_t ha = f2bf(a), hb = f2bf(b);
    hi = ha | (hb << 16);
    lo = pack2(a - bf2f(ha), b - bf2f(hb));
}

__device__ __forceinline__ void mma_bf16(float* c, const uint32_t* a, uint32_t b0, uint32_t b1) {
    asm volatile(
        "mma.sync.aligned.m16n8k16.row.col.f32.bf16.bf16.f32 "
        "{%0,%1,%2,%3},{%4,%5,%6,%7},{%8,%9},{%0,%1,%2,%3};"
        : "+f"(c[0]), "+f"(c[1]), "+f"(c[2]), "+f"(c[3])
        : "r"(a[0]), "r"(a[1]), "r"(a[2]), "r"(a[3]), "r"(b0), "r"(b1));
}

__device__ __forceinline__ void ldsm4t(uint32_t& a, uint32_t& b, uint32_t& c, uint32_t& d,
                                       uint32_t addr) {
    asm volatile("ldmatrix.sync.aligned.m8n8.x4.trans.shared.b16 {%0,%1,%2,%3}, [%4];"
        : "=r"(a), "=r"(b), "=r"(c), "=r"(d) : "r"(addr));
}

__device__ __forceinline__ void cp16(uint32_t dst, const float* src, bool pred) {
    int sz = pred ? 16 : 0;
    asm volatile("cp.async.cg.shared.global [%0], [%1], 16, %2;"
                 :: "r"(dst), "l"(src), "r"(sz));
}

// ---------------- tf32 conversion (elementwise, float4) ----------------
__global__ void cvt_tf32_kernel(const float* __restrict__ in, float* __restrict__ out, int n4)
{
    int i = blockIdx.x * blockDim.x + threadIdx.x;
    if (i < n4) {
        float4 v = ((const float4*)in)[i];
        v.x = to_tf32(v.x); v.y = to_tf32(v.y);
        v.z = to_tf32(v.z); v.w = to_tf32(v.w);
        ((float4*)out)[i] = v;
    }
}

// ---------------- tf32 GEMM with cp.async double buffering (proven) -------
#define GEMM_SMEM (4 * 128 * 32 * 4)   // 65536 B

template<int MODE>
__global__ __launch_bounds__(256) void mma_gemm(
    const float* __restrict__ Aop, const float* __restrict__ Wop,
    const float* __restrict__ bias_q, const float* __restrict__ bias_v,
    float* __restrict__ out)
{
    extern __shared__ float smg[];
    float* As = smg;                // [2][128*32]
    float* Bs = smg + 2*128*32;

    const int tid  = threadIdx.x;
    const int lane = tid & 31;
    const int warp = tid >> 5;
    const int wm   = (warp >> 2) * 64;
    const int wn   = (warp & 3) * 32;
    const int r    = lane >> 2;
    const int cg   = lane & 3;

    const int m0 = blockIdx.y * 128;
    const int n0 = blockIdx.x * 128;

    uint32_t asu = (uint32_t)__cvta_generic_to_shared(As);
    uint32_t bsu = (uint32_t)__cvta_generic_to_shared(Bs);

    const int srow = tid >> 3;
    const int sg   = tid & 7;

    float acc[4][4][4];
    #pragma unroll
    for (int i = 0; i < 4; i++)
        #pragma unroll
        for (int j = 0; j < 4; j++)
            #pragma unroll
            for (int q = 0; q < 4; q++) acc[i][j][q] = 0.f;

    const int NK = KDIM / 32;   // 24

    auto issue = [&](int kt, int s) {
        int k0 = kt * 32;
        #pragma unroll
        for (int i = 0; i < 4; i++) {
            int row = srow + 32*i;
            int sw  = ((sg ^ (row & 7)) << 2);
            uint32_t off = (uint32_t)((s*4096 + row*32 + sw) << 2);
            cp16(asu + off, &Aop[(size_t)(m0+row)*KDIM + k0 + sg*4], (m0+row) < MM);
            cp16(bsu + off, &Wop[(size_t)(n0+row)*KDIM + k0 + sg*4], true);
        }
    };

    issue(0, 0);
    asm volatile("cp.async.commit_group;");

    for (int kt = 0; kt < NK; kt++) {
        const int s = kt & 1;
        if (kt + 1 < NK) {
            issue(kt + 1, (kt + 1) & 1);
            asm volatile("cp.async.commit_group;");
            asm volatile("cp.async.wait_group 1;");
        } else {
            asm volatile("cp.async.wait_group 0;");
        }
        __syncthreads();

        const float* Ab = As + s*4096;
        const float* Bb = Bs + s*4096;

        #pragma unroll
        for (int kk = 0; kk < 32; kk += 8) {
            const int g0 = kk >> 2;
            const int c0 = ((g0 ^ r) << 2) + cg;
            const int c1 = (((g0 + 1) ^ r) << 2) + cg;
            uint32_t af[4][4], bf[4][2];
            #pragma unroll
            for (int mt = 0; mt < 4; mt++) {
                const float* p = &Ab[(wm + mt*16 + r)*32];
                af[mt][0] = __float_as_uint(p[c0]);
                af[mt][1] = __float_as_uint(p[8*32 + c0]);
                af[mt][2] = __float_as_uint(p[c1]);
                af[mt][3] = __float_as_uint(p[8*32 + c1]);
            }
            #pragma unroll
            for (int nt = 0; nt < 4; nt++) {
                const float* p = &Bb[(wn + nt*8 + r)*32];
                bf[nt][0] = __float_as_uint(p[c0]);
                bf[nt][1] = __float_as_uint(p[c1]);
            }
            #pragma unroll
            for (int mt = 0; mt < 4; mt++)
                #pragma unroll
                for (int nt = 0; nt < 4; nt++) {
                    asm volatile(
                        "mma.sync.aligned.m16n8k8.row.col.f32.tf32.tf32.f32 "
                        "{%0,%1,%2,%3},{%4,%5,%6,%7},{%8,%9},{%0,%1,%2,%3};"
                        : "+f"(acc[mt][nt][0]), "+f"(acc[mt][nt][1]),
                          "+f"(acc[mt][nt][2]), "+f"(acc[mt][nt][3])
                        : "r"(af[mt][0]), "r"(af[mt][1]),
                          "r"(af[mt][2]), "r"(af[mt][3]),
                          "r"(bf[nt][0]), "r"(bf[nt][1]));
                }
        }
        __syncthreads();
    }

    #pragma unroll
    for (int nt = 0; nt < 4; nt++) {
        int col = n0 + wn + nt*8 + 2*cg;
        if (MODE == 0) {
            int which = col / CC;
            int rem   = col - which*CC;
            int h     = rem >> 6;
            int d     = rem & 63;
            float b0 = (which == 0) ? bias_q[rem]   : (which == 2) ? bias_v[rem]   : 0.f;
            float b1 = (which == 0) ? bias_q[rem+1] : (which == 2) ? bias_v[rem+1] : 0.f;
            float* dst = (which == 0) ? g_q : (which == 1) ? g_k : g_v;
            #pragma unroll
            for (int mt = 0; mt < 4; mt++) {
                #pragma unroll
                for (int half = 0; half < 2; half++) {
                    int m = m0 + wm + mt*16 + r + half*8;
                    if (m < MM) {
                        int bb = m / NN, n = m - bb*NN;
                        float2 v = make_float2(acc[mt][nt][half*2]   + b0,
                                               acc[mt][nt][half*2+1] + b1);
                        *(float2*)&dst[(((size_t)bb*HH + h)*NN + n)*DD + d] = v;
                    }
                }
            }
        } else {
            float b0 = bias_q[col], b1 = bias_q[col+1];
            #pragma unroll
            for (int mt = 0; mt < 4; mt++) {
                #pragma unroll
                for (int half = 0; half < 2; half++) {
                    int m = m0 + wm + mt*16 + r + half*8;
                    if (m < MM) {
                        float2 v = make_float2(acc[mt][nt][half*2]   + b0,
                                               acc[mt][nt][half*2+1] + b1);
                        *(float2*)&out[(size_t)m*CC + col] = v;
                    }
                }
            }
        }
    }
}

// ---------------- RoPE ----------------
__global__ void rope_kernel(const float* __restrict__ rope)
{
    int idx = blockIdx.x * blockDim.x + threadIdx.x;
    const int total = BB*HH*(NN-1)*(DD/2);
    if (idx >= total) return;
    int pair = idx & 31;
    int rest = idx >> 5;
    int nr = rest % (NN-1);
    int bh = rest / (NN-1);
    int d0 = pair * 2;

    float s0 = rope[nr*2*DD + d0];
    float s1 = rope[nr*2*DD + d0 + 1];
    float c0 = rope[nr*2*DD + DD + d0];
    float c1 = rope[nr*2*DD + DD + d0 + 1];

    int base = (bh*NN + (nr + 1))*DD + d0;
    float2 q = *(float2*)&g_q[base];
    float2 k = *(float2*)&g_k[base];
    *(float2*)&g_q[base] = make_float2(q.x*c0 - q.y*s0, q.y*c1 + q.x*s1);
    *(float2*)&g_k[base] = make_float2(k.x*c0 - k.y*s0, k.y*c1 + k.x*s1);
}

// ---------------- Tensor-core flash attention v2 -----------------------
// 128 q-rows/block, 8 warps each owning 16 rows x full key range.
// P stays in registers (score C-frags == PV A-frags). V b-frags via
// ldmatrix.x4.trans. bf16x3 everywhere, max-free softmax.
#define AT_STR 36                          // u32 row stride (= 72 bf16)
#define ATTN3_SMEM (4*64*AT_STR*4)         // 36864 B

__global__ __launch_bounds__(256) void attn_mma_kernel()
{
    extern __shared__ uint32_t smu[];
    uint32_t* Kh = smu;
    uint32_t* Kl = Kh + 64*AT_STR;
    uint32_t* Vh = Kl + 64*AT_STR;
    uint32_t* Vl = Vh + 64*AT_STR;

    const int tid  = threadIdx.x;
    const int lane = tid & 31;
    const int wid  = tid >> 5;      // 0..7: rows wid*16 .. +15
    const int r    = lane >> 2;
    const int cg   = lane & 3;

    const int bh   = blockIdx.y;
    const int q0   = blockIdx.x * 128;
    const int base = bh * NN * DD;
    const float scale = 0.125f;

    const uint32_t vh_u = (uint32_t)__cvta_generic_to_shared(Vh);
    const uint32_t vl_u = (uint32_t)__cvta_generic_to_shared(Vl);
    // ldmatrix lane addressing: phase 0..3, row-in-phase 0..7
    const int crow = ((lane >> 3) & 1) * 8 + (lane & 7);   // key row within k16 chunk
    const int dcol = (lane >> 4) * 8;                      // d col offset within d16 pair

    // ---- Q fragments (bf16 hi/lo) ----
    uint32_t qh[4][4], ql[4][4];
    {
        int row0 = q0 + wid*16 + r;      if (row0 >= NN) row0 = 0;
        int row1 = q0 + wid*16 + r + 8;  if (row1 >= NN) row1 = 0;
        #pragma unroll
        for (int ks = 0; ks < 4; ks++) {
            float2 v;
            v = *(const float2*)&g_q[base + row0*DD + ks*16 + 2*cg];
            split2(v.x*scale, v.y*scale, qh[ks][0], ql[ks][0]);
            v = *(const float2*)&g_q[base + row1*DD + ks*16 + 2*cg];
            split2(v.x*scale, v.y*scale, qh[ks][1], ql[ks][1]);
            v = *(const float2*)&g_q[base + row0*DD + ks*16 + 2*cg + 8];
            split2(v.x*scale, v.y*scale, qh[ks][2], ql[ks][2]);
            v = *(const float2*)&g_q[base + row1*DD + ks*16 + 2*cg + 8];
            split2(v.x*scale, v.y*scale, qh[ks][3], ql[ks][3]);
        }
    }

    float o[8][4];
    #pragma unroll
    for (int i = 0; i < 8; i++)
        #pragma unroll
        for (int j = 0; j < 4; j++) o[i][j] = 0.f;
    float lp0 = 0.f, lp1 = 0.f;

    // staging indices (per thread: 4 chunks; c = key row, dq = float4 in row)
    float4 pk[4], pv[4];
    auto prefetch = [&](int t0) {
        #pragma unroll
        for (int s = 0; s < 4; s++) {
            int f4 = tid + 256*s;
            int c  = f4 >> 4;
            int dq = f4 & 15;
            int gr = t0 + c; if (gr >= NN) gr = NN - 1;
            pk[s] = *(const float4*)&g_k[base + gr*DD + dq*4];
            pv[s] = *(const float4*)&g_v[base + gr*DD + dq*4];
        }
    };
    prefetch(0);

    for (int t0 = 0; t0 < NN; t0 += 64) {
        __syncthreads();    // prior tile's smem reads complete

        // ---- convert + store staged K/V (hi/lo bf16) ----
        #pragma unroll
        for (int s = 0; s < 4; s++) {
            int f4 = tid + 256*s;
            int c  = f4 >> 4;
            int dq = f4 & 15;
            uint32_t h0, l0, h1, l1;
            split2(pk[s].x, pk[s].y, h0, l0); split2(pk[s].z, pk[s].w, h1, l1);
            Kh[c*AT_STR + dq*2] = h0;  Kh[c*AT_STR + dq*2 + 1] = h1;
            Kl[c*AT_STR + dq*2] = l0;  Kl[c*AT_STR + dq*2 + 1] = l1;
            split2(pv[s].x, pv[s].y, h0, l0); split2(pv[s].z, pv[s].w, h1, l1);
            Vh[c*AT_STR + dq*2] = h0;  Vh[c*AT_STR + dq*2 + 1] = h1;
            Vl[c*AT_STR + dq*2] = l0;  Vl[c*AT_STR + dq*2 + 1] = l1;
        }
        __syncthreads();

        if (t0 + 64 < NN) prefetch(t0 + 64);   // hidden under QK+PV

        // ---- scores: p[nt][4], nt over 8 key n-tiles ----
        float p[8][4];
        #pragma unroll
        for (int nt = 0; nt < 8; nt++)
            #pragma unroll
            for (int j = 0; j < 4; j++) p[nt][j] = 0.f;

        #pragma unroll
        for (int nt = 0; nt < 8; nt++) {
            int colr = nt*8 + r;
            #pragma unroll
            for (int ks = 0; ks < 4; ks++) {
                uint32_t b_h0 = Kh[colr*AT_STR + ks*8 + cg];
                uint32_t b_h1 = Kh[colr*AT_STR + ks*8 + cg + 4];
                uint32_t b_l0 = Kl[colr*AT_STR + ks*8 + cg];
                uint32_t b_l1 = Kl[colr*AT_STR + ks*8 + cg + 4];
                mma_bf16(p[nt], qh[ks], b_h0, b_h1);
                mma_bf16(p[nt], qh[ks], b_l0, b_l1);
                mma_bf16(p[nt], ql[ks], b_h0, b_h1);
            }
        }

        // ---- exp (max-free) + mask + row sums ----
        #pragma unroll
        for (int nt = 0; nt < 8; nt++) {
            int c01 = t0 + nt*8 + 2*cg;
            p[nt][0] = (c01     < NN) ? __expf(p[nt][0]) : 0.f;
            p[nt][1] = (c01 + 1 < NN) ? __expf(p[nt][1]) : 0.f;
            p[nt][2] = (c01     < NN) ? __expf(p[nt][2]) : 0.f;
            p[nt][3] = (c01 + 1 < NN) ? __expf(p[nt][3]) : 0.f;
            lp0 += p[nt][0] + p[nt][1];
            lp1 += p[nt][2] + p[nt][3];
        }

        // ---- o += P @ V : P frags direct from registers, V via ldmatrix ----
        #pragma unroll
        for (int ks = 0; ks < 4; ks++) {
            uint32_t ah[4], al[4];
            split2(p[2*ks  ][0], p[2*ks  ][1], ah[0], al[0]);
            split2(p[2*ks  ][2], p[2*ks  ][3], ah[1], al[1]);
            split2(p[2*ks+1][0], p[2*ks+1][1], ah[2], al[2]);
            split2(p[2*ks+1][2], p[2*ks+1][3], ah[3], al[3]);
            #pragma unroll
            for (int dtp = 0; dtp < 4; dtp++) {
                uint32_t off = (uint32_t)((((16*ks + crow)*2*AT_STR) + dtp*16 + dcol) << 1);
                uint32_t h0, h1, h2, h3, l0, l1, l2, l3;
                ldsm4t(h0, h1, h2, h3, vh_u + off);
                ldsm4t(l0, l1, l2, l3, vl_u + off);
                mma_bf16(o[2*dtp],   ah, h0, h1);
                mma_bf16(o[2*dtp],   ah, l0, l1);
                mma_bf16(o[2*dtp],   al, h0, h1);
                mma_bf16(o[2*dtp+1], ah, h2, h3);
                mma_bf16(o[2*dtp+1], ah, l2, l3);
                mma_bf16(o[2*dtp+1], al, h2, h3);
            }
        }
    }

    // ---- normalize + write (tf32-rounded for proj GEMM) ----
    lp0 += __shfl_xor_sync(0xffffffffu, lp0, 1);
    lp0 += __shfl_xor_sync(0xffffffffu, lp0, 2);
    lp1 += __shfl_xor_sync(0xffffffffu, lp1, 1);
    lp1 += __shfl_xor_sync(0xffffffffu, lp1, 2);
    const float inv0 = 1.f / lp0;
    const float inv1 = 1.f / lp1;

    const int b = bh / HH, h = bh % HH;
    const int grow0 = q0 + wid*16 + r;
    const int grow1 = grow0 + 8;
    #pragma unroll
    for (int dt = 0; dt < 8; dt++) {
        int d = dt*8 + 2*cg;
        if (grow0 < NN)
            *(float2*)&g_o[((size_t)(b*NN + grow0))*CC + h*DD + d] =
                make_float2(to_tf32(o[dt][0]*inv0), to_tf32(o[dt][1]*inv0));
        if (grow1 < NN)
            *(float2*)&g_o[((size_t)(b*NN + grow1))*CC + h*DD + d] =
                make_float2(to_tf32(o[dt][2]*inv1), to_tf32(o[dt][3]*inv1));
    }
}

// ---------------- launch ----------------
extern "C" void kernel_launch(void* const* d_in, const int* in_sizes, int n_in,
                              void* d_out, int out_size)
{
    const float* x      = (const float*)d_in[0];
    const float* rope   = (const float*)d_in[1];
    const float* qkv_w  = (const float*)d_in[2];
    const float* q_bias = (const float*)d_in[3];
    const float* v_bias = (const float*)d_in[4];
    const float* proj_w = (const float*)d_in[5];
    const float* proj_b = (const float*)d_in[6];
    float* out = (float*)d_out;

    cudaFuncSetAttribute(attn_mma_kernel,
                         cudaFuncAttributeMaxDynamicSharedMemorySize, ATTN3_SMEM);
    cudaFuncSetAttribute(mma_gemm<0>,
                         cudaFuncAttributeMaxDynamicSharedMemorySize, GEMM_SMEM);
    cudaFuncSetAttribute(mma_gemm<1>,
                         cudaFuncAttributeMaxDynamicSharedMemorySize, GEMM_SMEM);

    float* xr; cudaGetSymbolAddress((void**)&xr, g_xr);
    float* wq; cudaGetSymbolAddress((void**)&wq, g_wq);
    float* wp; cudaGetSymbolAddress((void**)&wp, g_wp);

    // 0. pre-round operands to tf32
    cvt_tf32_kernel<<<(MM*KDIM/4 + 255)/256, 256>>>(x, xr, MM*KDIM/4);
    cvt_tf32_kernel<<<(QKV_N*KDIM/4 + 255)/256, 256>>>(qkv_w, wq, QKV_N*KDIM/4);
    cvt_tf32_kernel<<<(CC*KDIM/4 + 255)/256, 256>>>(proj_w, wp, CC*KDIM/4);

    const int MB = (MM + 127) / 128;

    // 1. QKV GEMM -> g_q, g_k, g_v
    mma_gemm<0><<<dim3(QKV_N/128, MB), 256, GEMM_SMEM>>>(xr, wq, q_bias, v_bias, nullptr);

    // 2. RoPE
    int rtot = BB*HH*(NN-1)*(DD/2);
    rope_kernel<<<(rtot + 255)/256, 256>>>(rope);

    // 3. attention -> g_o (tf32-rounded); 128 q-rows per block
    attn_mma_kernel<<<dim3((NN + 127)/128, BB*HH), 256, ATTN3_SMEM>>>();

    // 4. output projection -> d_out
    float* go; cudaGetSymbolAddress((void**)&go, g_o);
    mma_gemm<1><<<dim3(CC/128, MB), 256, GEMM_SMEM>>>(go, wp, proj_b, nullptr, out);
}